// round 16
// baseline (speedup 1.0000x reference)
#include <cuda_runtime.h>
#include <math.h>
#include <stdint.h>

// QuadrotorDynamics: per-row map over (B,16) f32.
// Input row:  [0:3]=ang, [3:6]=pos(unused), [6:9]=rate, [9:12]=vel, [12:16]=cmd
// Output row: [0:3]=ang_dot, [3:6]=vel, [6:9]=rate_dot, [9:12]=vel_dot, [12:16]=0
//
// Smem-staged coalesced kernel, 512-row tiles (32 KB smem), 256 threads,
// 2 rows/thread. 256-bit hinted global accesses (ld evict_last / st
// evict_first, .v8.b32 form required on sm_100; measured neutral but free).
// Workload is at its compulsory-traffic roofline (256 MB/replay @ ~5.95 TB/s
// sustained -> ~43 us wall); this variant halves block count and doubles
// per-block store batching to probe burst/overhead sensitivity.
//
// Precision: theta uses PRECISE sincosf (cos(theta) is a denominator; rows
// with theta near pi/2 amplify __sincosf's 3.6e-7 abs error past 1e-3).
// phi/psi feed numerators/bounded products -> fast __sincosf is safe.

#define C_L      0.17f
#define C_MASS   0.68f
#define C_DARM   0.016f
#define C_KT     0.1f
#define C_KR     0.1f
#define C_IXX    0.007f
#define C_IYY    0.007f
#define C_IZZ    0.012f
#define C_GZ     9.8067f
#define C_707L   (0.707f * C_L)

#define TILE_ROWS 512

// Bank-conflict-avoiding swizzle on float4 index (generic in idx; for a
// 32B pair P both float4s share XOR term x=(P>>2)&7, all STS/LDS phases
// hit permutations of the 8 bank groups).
__device__ __forceinline__ int sw(int idx) { return idx ^ ((idx >> 3) & 7); }

// 32-byte global load with L2 evict_last hint.
__device__ __forceinline__ void ldg_keep8(const void* p, float4& lo, float4& hi)
{
    uint32_t u0,u1,u2,u3,u4,u5,u6,u7;
    asm volatile("ld.global.L2::evict_last.v8.b32 {%0,%1,%2,%3,%4,%5,%6,%7}, [%8];"
                 : "=r"(u0), "=r"(u1), "=r"(u2), "=r"(u3),
                   "=r"(u4), "=r"(u5), "=r"(u6), "=r"(u7)
                 : "l"(p));
    lo = make_float4(__uint_as_float(u0), __uint_as_float(u1),
                     __uint_as_float(u2), __uint_as_float(u3));
    hi = make_float4(__uint_as_float(u4), __uint_as_float(u5),
                     __uint_as_float(u6), __uint_as_float(u7));
}

// 32-byte global store with L2 evict_first (streaming) hint.
__device__ __forceinline__ void stg_stream8(void* p, float4 lo, float4 hi)
{
    asm volatile("st.global.L2::evict_first.v8.b32 [%0], {%1,%2,%3,%4,%5,%6,%7,%8};"
                 :: "l"(p),
                    "r"(__float_as_uint(lo.x)), "r"(__float_as_uint(lo.y)),
                    "r"(__float_as_uint(lo.z)), "r"(__float_as_uint(lo.w)),
                    "r"(__float_as_uint(hi.x)), "r"(__float_as_uint(hi.y)),
                    "r"(__float_as_uint(hi.z)), "r"(__float_as_uint(hi.w))
                 : "memory");
}

__device__ __forceinline__ void compute_row(
    const float4 x0, const float4 x1, const float4 x2, const float4 x3,
    float a0, float a1, float a2, float a3,
    float b0, float b1, float b2, float b3,
    float c0, float c1_, float c2_, float c3_,
    float4& o0, float4& o1, float4& o2)
{
    // thrusts = a*cmd^2 + b*cmd + c
    const float t0 = fmaf(fmaf(a0, x3.x, b0), x3.x, c0);
    const float t1 = fmaf(fmaf(a1, x3.y, b1), x3.y, c1_);
    const float t2 = fmaf(fmaf(a2, x3.z, b2), x3.z, c2_);
    const float t3 = fmaf(fmaf(a3, x3.w, b3), x3.w, c3_);

    // torques = TORQUE_MAT @ thrusts (constants folded)
    const float tqT = t0 + t1 + t2 + t3;
    const float tq1 = C_707L * ((t0 + t3) - (t1 + t2));
    const float tq2 = C_707L * ((t2 + t3) - (t0 + t1));
    const float tq3 = C_DARM * ((t1 + t3) - (t0 + t2));

    float s_phi, c_phi, s_th, c_th, s_psi, c_psi;
    __sincosf(x0.x, &s_phi, &c_phi);    // phi: numerators only -> fast OK
    sincosf(x0.y, &s_th,  &c_th);       // theta: denominator -> PRECISE
    __sincosf(x0.z, &s_psi, &c_psi);    // psi: bounded products -> fast OK

    const float p = x1.z, q = x1.w, r = x2.x;
    const float vx = x2.y, vy = x2.z, vz = x2.w;

    // ang_dot = inv(Mm) @ rate, closed form (det(Mm) = c_th)
    const float y2 = __fdividef(fmaf(s_phi, q, c_phi * r), c_th);
    const float y1 = c_phi * q - s_phi * r;
    const float y0 = fmaf(s_phi, y2, p);

    // rbi third column
    const float z0 = fmaf(c_phi * c_psi, s_th,  s_phi * s_psi);
    const float z1 = fmaf(c_phi * s_psi, s_th, -s_phi * c_psi);
    const float z2 = c_th * c_phi;

    // vel_dot = rbi[:,2]*(T/m) - KT*vel - GRAV
    const float Tm  = tqT * (1.0f / C_MASS);
    const float vd0 = fmaf(z0, Tm, -C_KT * vx);
    const float vd1 = fmaf(z1, Tm, -C_KT * vy);
    const float vd2 = fmaf(z2, Tm, -C_KT * vz) - C_GZ;

    // rate_dot = I_inv @ (tau - w x (I w) - KR*w)   (diagonal I)
    const float rd0 = (tq1 - q * r * (C_IZZ - C_IYY) - C_KR * p) * (1.0f / C_IXX);
    const float rd1 = (tq2 - r * p * (C_IXX - C_IZZ) - C_KR * q) * (1.0f / C_IYY);
    const float rd2 = (tq3 - p * q * (C_IYY - C_IXX) - C_KR * r) * (1.0f / C_IZZ);

    o0 = make_float4(y0,  y1,  y2,  vx);
    o1 = make_float4(vy,  vz,  rd0, rd1);
    o2 = make_float4(rd2, vd0, vd1, vd2);
}

__global__ void __launch_bounds__(256)
quad_dyn_kernel(const char* __restrict__ inb,
                char* __restrict__ outb,
                const float* __restrict__ ga,
                const float* __restrict__ gb,
                const float* __restrict__ gc,
                int n)
{
    __shared__ float4 s[TILE_ROWS * 4];   // 512 rows * 64 B = 32 KB

    const int tid = threadIdx.x;
    const int row0 = blockIdx.x * TILE_ROWS;
    const int rows_here = min(TILE_ROWS, n - row0);
    const int pairs_here = rows_here << 1;            // 32B pairs (even)
    const long long gpair = ((long long)row0) << 1;   // global 32B-pair base

    const float a0 = __ldg(&ga[0]), a1 = __ldg(&ga[1]), a2 = __ldg(&ga[2]), a3 = __ldg(&ga[3]);
    const float b0 = __ldg(&gb[0]), b1 = __ldg(&gb[1]), b2 = __ldg(&gb[2]), b3 = __ldg(&gb[3]);
    const float c0 = __ldg(&gc[0]), c1 = __ldg(&gc[1]), c2 = __ldg(&gc[2]), c3 = __ldg(&gc[3]);

    // ---- coalesced hinted 32B loads -> swizzled smem (4 phases) ----
    #pragma unroll
    for (int k = 0; k < 4; k++) {
        int P = tid + (k << 8);
        if (P < pairs_here) {
            float4 lo, hi;
            ldg_keep8(inb + ((gpair + P) << 5), lo, hi);
            const int x = (P >> 2) & 7;
            s[(2 * P)     ^ x] = lo;
            s[(2 * P + 1) ^ x] = hi;
        }
    }
    __syncthreads();

    // ---- compute: 2 rows per thread ----
    #pragma unroll
    for (int rr = 0; rr < 2; rr++) {
        const int row = tid + (rr << 8);
        if (row < rows_here) {
            const int i4 = row << 2;
            const float4 x0 = s[sw(i4 + 0)];   // ang0, ang1, ang2, pos0
            const float4 x1 = s[sw(i4 + 1)];   // pos1, pos2, rate0, rate1
            const float4 x2 = s[sw(i4 + 2)];   // rate2, vel0, vel1, vel2
            const float4 x3 = s[sw(i4 + 3)];   // cmd0..cmd3
            float4 o0, o1, o2;
            compute_row(x0, x1, x2, x3, a0,a1,a2,a3, b0,b1,b2,b3, c0,c1,c2,c3, o0, o1, o2);
            s[sw(i4 + 0)] = o0;
            s[sw(i4 + 1)] = o1;
            s[sw(i4 + 2)] = o2;
            s[sw(i4 + 3)] = make_float4(0.0f, 0.0f, 0.0f, 0.0f);
        }
    }
    __syncthreads();

    // ---- swizzled smem -> coalesced hinted 32B stores (4 phases) ----
    #pragma unroll
    for (int k = 0; k < 4; k++) {
        int P = tid + (k << 8);
        if (P < pairs_here) {
            const int x = (P >> 2) & 7;
            const float4 lo = s[(2 * P)     ^ x];
            const float4 hi = s[(2 * P + 1) ^ x];
            stg_stream8(outb + ((gpair + P) << 5), lo, hi);
        }
    }
}

extern "C" void kernel_launch(void* const* d_in, const int* in_sizes, int n_in,
                              void* d_out, int out_size)
{
    // metadata order: t (scalar, unused), input (B*16 f32), a(4), b(4), c(4)
    const char*  in  = (const char*)d_in[1];
    const float* a   = (const float*)d_in[2];
    const float* b   = (const float*)d_in[3];
    const float* c   = (const float*)d_in[4];
    char* out = (char*)d_out;

    const int n = in_sizes[1] / 16;
    const int blocks = (n + TILE_ROWS - 1) / TILE_ROWS;   // 512 rows per block
    quad_dyn_kernel<<<blocks, 256>>>(in, out, a, b, c, n);
}

// round 17
// speedup vs baseline: 1.0453x; 1.0453x over previous
#include <cuda_runtime.h>
#include <math.h>
#include <stdint.h>

// QuadrotorDynamics: per-row map over (B,16) f32.
// Input row:  [0:3]=ang, [3:6]=pos(unused), [6:9]=rate, [9:12]=vel, [12:16]=cmd
// Output row: [0:3]=ang_dot, [3:6]=vel, [6:9]=rate_dot, [9:12]=vel_dot, [12:16]=0
//
// FINAL (session best, 43.0 us wall): smem-staged coalesced kernel with
// 256-bit global accesses, 256-row tiles, 1 row/thread (regs=36, occ~68%).
//
// The workload sits at its compulsory-traffic roofline: 256 MB/replay
// (every 32B sector of input and output verified live) over ~5.95 TB/s
// sustained replay-loop HBM -> ~43 us wall floor. Confirmed by six
// architectures within +-0.2 us (coalesced LDG, smem-staged, serial TMA,
// persistent TMA x3/x6 per SM, hinted variants); the only designs that
// left the plateau were occupancy-starved ones that regressed (512-row
// tiles: regs 56, occ 45%, 45.1 us). L2 eviction hints retained (measured
// neutral; sm_100 requires the .v8.b32 form).
//
// Precision: theta uses PRECISE sincosf (cos(theta) is a denominator; rows
// with theta near pi/2 amplify __sincosf's 3.6e-7 abs error past 1e-3).
// phi/psi feed numerators/bounded products -> fast __sincosf is safe.

#define C_L      0.17f
#define C_MASS   0.68f
#define C_DARM   0.016f
#define C_KT     0.1f
#define C_KR     0.1f
#define C_IXX    0.007f
#define C_IYY    0.007f
#define C_IZZ    0.012f
#define C_GZ     9.8067f
#define C_707L   (0.707f * C_L)

// Bank-conflict-avoiding swizzle on float4 index (row-major readback maps
// each 8-lane LDS.128 phase to 8 distinct bank groups). For a pair P the
// two float4s (2P, 2P+1) share XOR term x=(P>>2)&7; staged STS/LDS phases
// remain conflict-free (bank-group sets are permutations of 0..7).
__device__ __forceinline__ int sw(int idx) { return idx ^ ((idx >> 3) & 7); }

// 32-byte global load with L2 evict_last (keep-resident) hint.
__device__ __forceinline__ void ldg_keep8(const void* p, float4& lo, float4& hi)
{
    uint32_t u0,u1,u2,u3,u4,u5,u6,u7;
    asm volatile("ld.global.L2::evict_last.v8.b32 {%0,%1,%2,%3,%4,%5,%6,%7}, [%8];"
                 : "=r"(u0), "=r"(u1), "=r"(u2), "=r"(u3),
                   "=r"(u4), "=r"(u5), "=r"(u6), "=r"(u7)
                 : "l"(p));
    lo = make_float4(__uint_as_float(u0), __uint_as_float(u1),
                     __uint_as_float(u2), __uint_as_float(u3));
    hi = make_float4(__uint_as_float(u4), __uint_as_float(u5),
                     __uint_as_float(u6), __uint_as_float(u7));
}

// 32-byte global store with L2 evict_first (streaming) hint.
__device__ __forceinline__ void stg_stream8(void* p, float4 lo, float4 hi)
{
    asm volatile("st.global.L2::evict_first.v8.b32 [%0], {%1,%2,%3,%4,%5,%6,%7,%8};"
                 :: "l"(p),
                    "r"(__float_as_uint(lo.x)), "r"(__float_as_uint(lo.y)),
                    "r"(__float_as_uint(lo.z)), "r"(__float_as_uint(lo.w)),
                    "r"(__float_as_uint(hi.x)), "r"(__float_as_uint(hi.y)),
                    "r"(__float_as_uint(hi.z)), "r"(__float_as_uint(hi.w))
                 : "memory");
}

__device__ __forceinline__ void compute_row(
    const float4 x0, const float4 x1, const float4 x2, const float4 x3,
    float a0, float a1, float a2, float a3,
    float b0, float b1, float b2, float b3,
    float c0, float c1_, float c2_, float c3_,
    float4& o0, float4& o1, float4& o2)
{
    // thrusts = a*cmd^2 + b*cmd + c
    const float t0 = fmaf(fmaf(a0, x3.x, b0), x3.x, c0);
    const float t1 = fmaf(fmaf(a1, x3.y, b1), x3.y, c1_);
    const float t2 = fmaf(fmaf(a2, x3.z, b2), x3.z, c2_);
    const float t3 = fmaf(fmaf(a3, x3.w, b3), x3.w, c3_);

    // torques = TORQUE_MAT @ thrusts (constants folded)
    const float tqT = t0 + t1 + t2 + t3;
    const float tq1 = C_707L * ((t0 + t3) - (t1 + t2));
    const float tq2 = C_707L * ((t2 + t3) - (t0 + t1));
    const float tq3 = C_DARM * ((t1 + t3) - (t0 + t2));

    float s_phi, c_phi, s_th, c_th, s_psi, c_psi;
    __sincosf(x0.x, &s_phi, &c_phi);    // phi: numerators only -> fast OK
    sincosf(x0.y, &s_th,  &c_th);       // theta: denominator -> PRECISE
    __sincosf(x0.z, &s_psi, &c_psi);    // psi: bounded products -> fast OK

    const float p = x1.z, q = x1.w, r = x2.x;
    const float vx = x2.y, vy = x2.z, vz = x2.w;

    // ang_dot = inv(Mm) @ rate, closed form (det(Mm) = c_th)
    const float y2 = __fdividef(fmaf(s_phi, q, c_phi * r), c_th);
    const float y1 = c_phi * q - s_phi * r;
    const float y0 = fmaf(s_phi, y2, p);

    // rbi third column
    const float z0 = fmaf(c_phi * c_psi, s_th,  s_phi * s_psi);
    const float z1 = fmaf(c_phi * s_psi, s_th, -s_phi * c_psi);
    const float z2 = c_th * c_phi;

    // vel_dot = rbi[:,2]*(T/m) - KT*vel - GRAV
    const float Tm  = tqT * (1.0f / C_MASS);
    const float vd0 = fmaf(z0, Tm, -C_KT * vx);
    const float vd1 = fmaf(z1, Tm, -C_KT * vy);
    const float vd2 = fmaf(z2, Tm, -C_KT * vz) - C_GZ;

    // rate_dot = I_inv @ (tau - w x (I w) - KR*w)   (diagonal I)
    const float rd0 = (tq1 - q * r * (C_IZZ - C_IYY) - C_KR * p) * (1.0f / C_IXX);
    const float rd1 = (tq2 - r * p * (C_IXX - C_IZZ) - C_KR * q) * (1.0f / C_IYY);
    const float rd2 = (tq3 - p * q * (C_IYY - C_IXX) - C_KR * r) * (1.0f / C_IZZ);

    o0 = make_float4(y0,  y1,  y2,  vx);
    o1 = make_float4(vy,  vz,  rd0, rd1);
    o2 = make_float4(rd2, vd0, vd1, vd2);
}

__global__ void __launch_bounds__(256)
quad_dyn_kernel(const char* __restrict__ inb,
                char* __restrict__ outb,
                const float* __restrict__ ga,
                const float* __restrict__ gb,
                const float* __restrict__ gc,
                int n)
{
    __shared__ float4 s[1024];   // 256 rows * 4 float4 = 16 KB

    const int tid = threadIdx.x;
    const int row0 = blockIdx.x << 8;            // 256 rows per block
    const int rows_here = min(256, n - row0);
    const int pairs_here = rows_here << 1;       // 32B pairs this tile (even)
    const long long gpair = ((long long)row0) << 1;   // global 32B-pair base

    const float a0 = __ldg(&ga[0]), a1 = __ldg(&ga[1]), a2 = __ldg(&ga[2]), a3 = __ldg(&ga[3]);
    const float b0 = __ldg(&gb[0]), b1 = __ldg(&gb[1]), b2 = __ldg(&gb[2]), b3 = __ldg(&gb[3]);
    const float c0 = __ldg(&gc[0]), c1 = __ldg(&gc[1]), c2 = __ldg(&gc[2]), c3 = __ldg(&gc[3]);

    // ---- coalesced hinted 32B loads -> swizzled smem ----
    #pragma unroll
    for (int k = 0; k < 2; k++) {
        int P = tid + (k << 8);
        if (P < pairs_here) {
            float4 lo, hi;
            ldg_keep8(inb + ((gpair + P) << 5), lo, hi);
            const int x = (P >> 2) & 7;
            s[(2 * P)     ^ x] = lo;
            s[(2 * P + 1) ^ x] = hi;
        }
    }
    __syncthreads();

    if (tid < rows_here) {
        const int i4 = tid << 2;
        const float4 x0 = s[sw(i4 + 0)];   // ang0, ang1, ang2, pos0
        const float4 x1 = s[sw(i4 + 1)];   // pos1, pos2, rate0, rate1
        const float4 x2 = s[sw(i4 + 2)];   // rate2, vel0, vel1, vel2
        const float4 x3 = s[sw(i4 + 3)];   // cmd0..cmd3
        float4 o0, o1, o2;
        compute_row(x0, x1, x2, x3, a0,a1,a2,a3, b0,b1,b2,b3, c0,c1,c2,c3, o0, o1, o2);
        s[sw(i4 + 0)] = o0;
        s[sw(i4 + 1)] = o1;
        s[sw(i4 + 2)] = o2;
        s[sw(i4 + 3)] = make_float4(0.0f, 0.0f, 0.0f, 0.0f);
    }
    __syncthreads();

    // ---- swizzled smem -> coalesced hinted 32B stores ----
    #pragma unroll
    for (int k = 0; k < 2; k++) {
        int P = tid + (k << 8);
        if (P < pairs_here) {
            const int x = (P >> 2) & 7;
            const float4 lo = s[(2 * P)     ^ x];
            const float4 hi = s[(2 * P + 1) ^ x];
            stg_stream8(outb + ((gpair + P) << 5), lo, hi);
        }
    }
}

extern "C" void kernel_launch(void* const* d_in, const int* in_sizes, int n_in,
                              void* d_out, int out_size)
{
    // metadata order: t (scalar, unused), input (B*16 f32), a(4), b(4), c(4)
    const char*  in  = (const char*)d_in[1];
    const float* a   = (const float*)d_in[2];
    const float* b   = (const float*)d_in[3];
    const float* c   = (const float*)d_in[4];
    char* out = (char*)d_out;

    const int n = in_sizes[1] / 16;
    const int threads = 256;
    const int blocks = (n + threads - 1) / threads;   // 256 rows per block
    quad_dyn_kernel<<<blocks, threads>>>(in, out, a, b, c, n);
}